// round 6
// baseline (speedup 1.0000x reference)
#include <cuda_runtime.h>
#include <cuda_bf16.h>
#include <cuda_fp16.h>
#include <cstdint>
#include <cstddef>

// Problem constants
#define BATCH   4
#define S_LEN   2048
#define D_MODEL 1024
#define NHEAD   16
#define HEAD_D  64
#define TDQ     (3 * D_MODEL)          // 3072
#define M_ROWS  (BATCH * S_LEN)        // 8192
#define KDIM    D_MODEL                // 1024
#define BH      (BATCH * NHEAD)        // 64

// ---------------------------------------------------------------------------
// Scratch (__device__ globals; allocation-free rule)
// ---------------------------------------------------------------------------
__device__ __align__(128) float         g_qkv   [(size_t)M_ROWS * TDQ];
__device__ __align__(128) __nv_bfloat16 g_x_hi  [(size_t)M_ROWS * KDIM];
__device__ __align__(128) __nv_bfloat16 g_x_lo  [(size_t)M_ROWS * KDIM];
__device__ __align__(128) __nv_bfloat16 g_wq_hi [(size_t)TDQ    * KDIM];
__device__ __align__(128) __nv_bfloat16 g_wq_lo [(size_t)TDQ    * KDIM];
__device__ __align__(128) __nv_bfloat16 g_wo_hi [(size_t)D_MODEL* KDIM];
__device__ __align__(128) __nv_bfloat16 g_wo_lo [(size_t)D_MODEL* KDIM];
__device__ __align__(128) __nv_bfloat16 g_at_hi [(size_t)M_ROWS * D_MODEL];
__device__ __align__(128) __nv_bfloat16 g_at_lo [(size_t)M_ROWS * D_MODEL];
// attention-ready planes
__device__ __align__(128) __nv_bfloat16 g_q_hi  [(size_t)BH * S_LEN * HEAD_D];
__device__ __align__(128) __nv_bfloat16 g_q_lo  [(size_t)BH * S_LEN * HEAD_D];
__device__ __align__(128) __nv_bfloat16 g_k_hi  [(size_t)BH * S_LEN * HEAD_D];
__device__ __align__(128) __nv_bfloat16 g_k_lo  [(size_t)BH * S_LEN * HEAD_D];
__device__ __align__(128) __half        g_vt    [(size_t)BH * HEAD_D * S_LEN];

// ---------------------------------------------------------------------------
// Helpers
// ---------------------------------------------------------------------------
__device__ __forceinline__ uint32_t smem_u32(const void* p) {
    uint32_t a;
    asm("{ .reg .u64 t; cvta.to.shared.u64 t, %1; cvt.u32.u64 %0, t; }"
        : "=r"(a) : "l"(p));
    return a;
}

#define CP_ASYNC16(saddr, gptr) \
    asm volatile("cp.async.cg.shared.global [%0], [%1], 16;" :: "r"(saddr), "l"(gptr))
#define CP_COMMIT() asm volatile("cp.async.commit_group;" ::: "memory")
#define CP_WAIT0()  asm volatile("cp.async.wait_group 0;" ::: "memory")
#define CP_WAIT1()  asm volatile("cp.async.wait_group 1;" ::: "memory")

__device__ __forceinline__ void ldsm4(uint32_t* r, uint32_t addr) {
    asm volatile("ldmatrix.sync.aligned.m8n8.x4.shared.b16 {%0,%1,%2,%3}, [%4];"
                 : "=r"(r[0]), "=r"(r[1]), "=r"(r[2]), "=r"(r[3]) : "r"(addr));
}
__device__ __forceinline__ void ldsm2(uint32_t* r, uint32_t addr) {
    asm volatile("ldmatrix.sync.aligned.m8n8.x2.shared.b16 {%0,%1}, [%2];"
                 : "=r"(r[0]), "=r"(r[1]) : "r"(addr));
}
__device__ __forceinline__ void mma16816(float* d, const uint32_t* a, const uint32_t* b) {
    asm volatile(
        "mma.sync.aligned.m16n8k16.row.col.f32.bf16.bf16.f32 "
        "{%0,%1,%2,%3}, {%4,%5,%6,%7}, {%8,%9}, {%0,%1,%2,%3};"
        : "+f"(d[0]), "+f"(d[1]), "+f"(d[2]), "+f"(d[3])
        : "r"(a[0]), "r"(a[1]), "r"(a[2]), "r"(a[3]), "r"(b[0]), "r"(b[1]));
}
__device__ __forceinline__ void mma16816h(float* d, const uint32_t* a, const uint32_t* b) {
    asm volatile(
        "mma.sync.aligned.m16n8k16.row.col.f32.f16.f16.f32 "
        "{%0,%1,%2,%3}, {%4,%5,%6,%7}, {%8,%9}, {%0,%1,%2,%3};"
        : "+f"(d[0]), "+f"(d[1]), "+f"(d[2]), "+f"(d[3])
        : "r"(a[0]), "r"(a[1]), "r"(a[2]), "r"(a[3]), "r"(b[0]), "r"(b[1]));
}

__device__ __forceinline__ void split1(float x, __nv_bfloat16& h, __nv_bfloat16& l) {
    h = __float2bfloat16(x);
    l = __float2bfloat16(x - __bfloat162float(h));
}
__device__ __forceinline__ void split2_pack(float x, float y, uint32_t& hi, uint32_t& lo) {
    __nv_bfloat16 hx, lx, hy, ly;
    split1(x, hx, lx); split1(y, hy, ly);
    __nv_bfloat162 th(hx, hy), tl(lx, ly);
    hi = *(uint32_t*)&th; lo = *(uint32_t*)&tl;
}
__device__ __forceinline__ uint32_t pack_h2(float x, float y) {
    __half2 h = __floats2half2_rn(x, y);
    return *(uint32_t*)&h;
}

// ---------------------------------------------------------------------------
// fp32 -> (bf16 hi, bf16 lo) split
// ---------------------------------------------------------------------------
__global__ void __launch_bounds__(256)
split_kernel(const float4* __restrict__ src, __nv_bfloat162* __restrict__ hi,
             __nv_bfloat162* __restrict__ lo, int n4)
{
    int i = blockIdx.x * blockDim.x + threadIdx.x;
    if (i >= n4) return;
    float4 v = src[i];
    __nv_bfloat16 hx, lx, hy, ly, hz, lz, hw, lw;
    split1(v.x, hx, lx); split1(v.y, hy, ly);
    split1(v.z, hz, lz); split1(v.w, hw, lw);
    hi[2 * i + 0] = __nv_bfloat162(hx, hy);
    hi[2 * i + 1] = __nv_bfloat162(hz, hw);
    lo[2 * i + 0] = __nv_bfloat162(lx, ly);
    lo[2 * i + 1] = __nv_bfloat162(lz, lw);
}

// ---------------------------------------------------------------------------
// Split-bf16 HMMA GEMM (NT): 128(M) x 256(N) CTA tile, BK=32, 8 warps as
// 2(M) x 4(N), 64x64 warp tile. 3-stage cp.async pipeline (wait_group 1).
// ---------------------------------------------------------------------------
#define ROWB   80
#define A_ARR  (128 * ROWB)             // 10240
#define B_ARR  (256 * ROWB)             // 20480
#define STAGE_B (2 * A_ARR + 2 * B_ARR) // 61440
#define GEMM_SMEM (3 * STAGE_B)         // 184320

__global__ void __launch_bounds__(256, 1)
gemm_hmma(const __nv_bfloat16* __restrict__ Ahi, const __nv_bfloat16* __restrict__ Alo,
          const __nv_bfloat16* __restrict__ Bhi, const __nv_bfloat16* __restrict__ Blo,
          const float* __restrict__ bias, float* __restrict__ C,
          int M, int N, int K)
{
    extern __shared__ char sm[];
    const int tid  = threadIdx.x;
    const int wid  = tid >> 5;
    const int lane = tid & 31;
    const int wm   = wid & 1;           // 0..1 (M)
    const int wn   = wid >> 1;          // 0..3 (N)
    const int row0 = blockIdx.y * 128;
    const int col0 = blockIdx.x * 256;

    const uint32_t smb = smem_u32(sm);
    const int lr = tid >> 2;            // 0..63
    const int lc = tid & 3;             // 16B chunk

    auto ld_chunk = [&](int i, int stage) {
        const int k0 = i * 32;
        uint32_t sb = smb + stage * STAGE_B;
        #pragma unroll
        for (int rep = 0; rep < 2; rep++) {
            int rr = lr + rep * 64;
            size_t go = (size_t)(row0 + rr) * K + k0 + lc * 8;
            uint32_t so = rr * ROWB + lc * 16;
            CP_ASYNC16(sb +         so, Ahi + go);
            CP_ASYNC16(sb + A_ARR + so, Alo + go);
        }
        #pragma unroll
        for (int rep = 0; rep < 4; rep++) {
            int rr = lr + rep * 64;
            size_t go = (size_t)(col0 + rr) * K + k0 + lc * 8;
            uint32_t so = rr * ROWB + lc * 16;
            CP_ASYNC16(sb + 2 * A_ARR +         so, Bhi + go);
            CP_ASYNC16(sb + 2 * A_ARR + B_ARR + so, Blo + go);
        }
    };

    float acc[4][8][4];
    #pragma unroll
    for (int i = 0; i < 4; i++)
        #pragma unroll
        for (int j = 0; j < 8; j++)
            #pragma unroll
            for (int v = 0; v < 4; v++) acc[i][j][v] = 0.f;

    const int arow = (lane & 7) + ((lane >> 3) & 1) * 8;
    const int akb  = (lane >> 4) * 16;
    const uint32_t aoff = (uint32_t)((wm * 64 + arow) * ROWB + akb);
    const uint32_t boff = (uint32_t)((wn * 64 + (lane & 7)) * ROWB + ((lane >> 3) & 1) * 16);

    const int NC = K / 32;              // 32 chunks
    // prologue: 2 chunks in flight
    ld_chunk(0, 0); CP_COMMIT();
    ld_chunk(1, 1); CP_COMMIT();

    int st = 0;
    for (int i = 0; i < NC; i++) {
        if (i < NC - 1) { CP_WAIT1(); } else { CP_WAIT0(); }
        __syncthreads();
        if (i + 2 < NC) {
            int s2 = st + 2; if (s2 >= 3) s2 -= 3;
            ld_chunk(i + 2, s2);
            CP_COMMIT();
        }

        const uint32_t sA  = smb + st * STAGE_B;
        const uint32_t sAl = sA + A_ARR;
        const uint32_t sB  = sA + 2 * A_ARR;
        const uint32_t sBl = sB + B_ARR;

        #pragma unroll
        for (int ks = 0; ks < 2; ks++) {
            uint32_t ah[4][4], al[4][4], bh[8][2], bl[8][2];
            #pragma unroll
            for (int fi = 0; fi < 4; fi++) {
                ldsm4(ah[fi], sA  + aoff + fi * 16 * ROWB + ks * 32);
                ldsm4(al[fi], sAl + aoff + fi * 16 * ROWB + ks * 32);
            }
            #pragma unroll
            for (int fj = 0; fj < 8; fj++) {
                ldsm2(bh[fj], sB  + boff + fj * 8 * ROWB + ks * 32);
                ldsm2(bl[fj], sBl + boff + fj * 8 * ROWB + ks * 32);
            }
            #pragma unroll
            for (int fi = 0; fi < 4; fi++)
                #pragma unroll
                for (int fj = 0; fj < 8; fj++) {
                    mma16816(acc[fi][fj], ah[fi], bh[fj]);
                    mma16816(acc[fi][fj], ah[fi], bl[fj]);
                    mma16816(acc[fi][fj], al[fi], bh[fj]);
                }
        }
        if (++st == 3) st = 0;
    }

    #pragma unroll
    for (int fi = 0; fi < 4; fi++) {
        const int r = row0 + wm * 64 + fi * 16 + (lane >> 2);
        #pragma unroll
        for (int fj = 0; fj < 8; fj++) {
            const int cc = col0 + wn * 64 + fj * 8 + (lane & 3) * 2;
            float2 bb = *(const float2*)&bias[cc];
            float2 v0 = make_float2(acc[fi][fj][0] + bb.x, acc[fi][fj][1] + bb.y);
            float2 v1 = make_float2(acc[fi][fj][2] + bb.x, acc[fi][fj][3] + bb.y);
            *(float2*)&C[(size_t)r * N + cc]       = v0;
            *(float2*)&C[(size_t)(r + 8) * N + cc] = v1;
        }
    }
}

// ---------------------------------------------------------------------------
// Prep: qkv fp32 -> Q/K bf16 hi+lo planes [bh][s][64] (Q scaled 1/8),
//       V^T fp16 plane [bh][d][s].
// ---------------------------------------------------------------------------
__global__ void __launch_bounds__(256)
prep_qkv(const float* __restrict__ qkv,
         __nv_bfloat16* __restrict__ qh, __nv_bfloat16* __restrict__ ql,
         __nv_bfloat16* __restrict__ kh, __nv_bfloat16* __restrict__ kl,
         __half* __restrict__ vt)
{
    const int s  = blockIdx.x * 256 + threadIdx.x;
    const int bh = blockIdx.y;
    const int b  = bh >> 4;
    const int h  = bh & 15;
    const float* src = qkv + ((size_t)(b * S_LEN + s)) * TDQ + h * 3 * HEAD_D;

    __nv_bfloat16* qhp = qh + ((size_t)bh * S_LEN + s) * HEAD_D;
    __nv_bfloat16* qlp = ql + ((size_t)bh * S_LEN + s) * HEAD_D;
    __nv_bfloat16* khp = kh + ((size_t)bh * S_LEN + s) * HEAD_D;
    __nv_bfloat16* klp = kl + ((size_t)bh * S_LEN + s) * HEAD_D;

    #pragma unroll
    for (int j = 0; j < 16; j++) {
        float4 qv = *(const float4*)(src + 4 * j);
        float4 kv = *(const float4*)(src + HEAD_D + 4 * j);
        __nv_bfloat16 hh, ll;
        split1(qv.x * 0.125f, hh, ll); qhp[4*j+0] = hh; qlp[4*j+0] = ll;
        split1(qv.y * 0.125f, hh, ll); qhp[4*j+1] = hh; qlp[4*j+1] = ll;
        split1(qv.z * 0.125f, hh, ll); qhp[4*j+2] = hh; qlp[4*j+2] = ll;
        split1(qv.w * 0.125f, hh, ll); qhp[4*j+3] = hh; qlp[4*j+3] = ll;
        split1(kv.x, hh, ll); khp[4*j+0] = hh; klp[4*j+0] = ll;
        split1(kv.y, hh, ll); khp[4*j+1] = hh; klp[4*j+1] = ll;
        split1(kv.z, hh, ll); khp[4*j+2] = hh; klp[4*j+2] = ll;
        split1(kv.w, hh, ll); khp[4*j+3] = hh; klp[4*j+3] = ll;
    }
    #pragma unroll
    for (int j = 0; j < 16; j++) {
        float4 vv = *(const float4*)(src + 2 * HEAD_D + 4 * j);
        #pragma unroll
        for (int e = 0; e < 4; e++) {
            float val = (e == 0) ? vv.x : (e == 1) ? vv.y : (e == 2) ? vv.z : vv.w;
            int d = 4 * j + e;
            vt[((size_t)bh * HEAD_D + d) * S_LEN + s] = __float2half(val);
        }
    }
}

// ---------------------------------------------------------------------------
// Flash attention on HMMA. 128 q rows/CTA, 8 warps x 16 rows, 64-key tiles.
// QK^T: 3-pass bf16 split. PV: single-pass fp16. 3-stage cp.async pipeline.
// ---------------------------------------------------------------------------
#define AROW     144
#define Q_ARR    (128 * AROW)          // 18432
#define T_ARR    (64 * AROW)           // 9216
#define T_STAGE  (3 * T_ARR)           // 27648 (Kh, Kl, V)
#define ATTN_SMEM (2 * Q_ARR + 3 * T_STAGE)   // 119808

__global__ void __launch_bounds__(256, 1)
attn_mma(const __nv_bfloat16* __restrict__ qh, const __nv_bfloat16* __restrict__ ql,
         const __nv_bfloat16* __restrict__ kh, const __nv_bfloat16* __restrict__ kl,
         const __half* __restrict__ vt,
         __nv_bfloat16* __restrict__ outh, __nv_bfloat16* __restrict__ outl)
{
    extern __shared__ char sm[];
    const uint32_t smb = smem_u32(sm);
    const int tid  = threadIdx.x;
    const int wid  = tid >> 5;
    const int lane = tid & 31;
    const int bh = blockIdx.y;
    const int qb = blockIdx.x;

    const __nv_bfloat16* Qh = qh + ((size_t)bh * S_LEN + qb * 128) * HEAD_D;
    const __nv_bfloat16* Ql = ql + ((size_t)bh * S_LEN + qb * 128) * HEAD_D;
    const __nv_bfloat16* Kh = kh + (size_t)bh * S_LEN * HEAD_D;
    const __nv_bfloat16* Kl = kl + (size_t)bh * S_LEN * HEAD_D;
    const __half*        Vt = vt + (size_t)bh * HEAD_D * S_LEN;

    auto ld_tile = [&](int kt, int st) {
        const int k0 = kt * 64;
        const uint32_t sb = smb + 2 * Q_ARR + st * T_STAGE;
        #pragma unroll
        for (int rep = 0; rep < 2; rep++) {
            int idx = tid + rep * 256;        // 0..511
            int row = idx >> 3;               // 0..63
            int ch  = idx & 7;
            uint32_t so = row * AROW + ch * 16;
            CP_ASYNC16(sb +             so, Kh + (size_t)(k0 + row) * HEAD_D + ch * 8);
            CP_ASYNC16(sb + T_ARR +     so, Kl + (size_t)(k0 + row) * HEAD_D + ch * 8);
            CP_ASYNC16(sb + 2 * T_ARR + so, Vt + (size_t)row * S_LEN + k0 + ch * 8);
        }
    };

    // group 0: Q + tile 0; group 1: tile 1
    #pragma unroll
    for (int rep = 0; rep < 4; rep++) {
        int idx = tid + rep * 256;
        int row = idx >> 3;
        int ch  = idx & 7;
        uint32_t so = row * AROW + ch * 16;
        CP_ASYNC16(smb +         so, Qh + (size_t)row * HEAD_D + ch * 8);
        CP_ASYNC16(smb + Q_ARR + so, Ql + (size_t)row * HEAD_D + ch * 8);
    }
    ld_tile(0, 0);
    CP_COMMIT();
    ld_tile(1, 1);
    CP_COMMIT();

    // Q fragments (need group 0 done)
    CP_WAIT1();
    __syncthreads();
    const int arow = (lane & 7) + ((lane >> 3) & 1) * 8;
    const int akb  = (lane >> 4) * 16;
    const uint32_t qbase = smb + (uint32_t)((wid * 16 + arow) * AROW + akb);
    uint32_t qfh[4][4], qfl[4][4];
    #pragma unroll
    for (int kk = 0; kk < 4; kk++) {
        ldsm4(qfh[kk], qbase + kk * 32);
        ldsm4(qfl[kk], qbase + Q_ARR + kk * 32);
    }

    float o[8][4];
    #pragma unroll
    for (int nf = 0; nf < 8; nf++)
        #pragma unroll
        for (int v = 0; v < 4; v++) o[nf][v] = 0.f;
    float m0 = -1e30f, m1 = -1e30f, l0 = 0.f, l1 = 0.f;

    const uint32_t bo = (uint32_t)((lane & 7) * AROW + ((lane >> 3) & 1) * 16);
    const int NT = S_LEN / 64;

    int st = 0;
    for (int kt = 0; kt < NT; kt++) {
        if (kt < NT - 1) { CP_WAIT1(); } else { CP_WAIT0(); }
        __syncthreads();
        if (kt + 2 < NT) {
            int s2 = st + 2; if (s2 >= 3) s2 -= 3;
            ld_tile(kt + 2, s2);
            CP_COMMIT();
        }

        const uint32_t base_k = smb + 2 * Q_ARR + st * T_STAGE;
        const uint32_t base_v = base_k + 2 * T_ARR;

        float s_[8][4];
        #pragma unroll
        for (int nf = 0; nf < 8; nf++)
            #pragma unroll
            for (int v = 0; v < 4; v++) s_[nf][v] = 0.f;

        #pragma unroll
        for (int nf = 0; nf < 8; nf++) {
            #pragma unroll
            for (int kk = 0; kk < 4; kk++) {
                uint32_t addr = base_k + bo + nf * 8 * AROW + kk * 32;
                uint32_t kbh[2], kbl[2];
                ldsm2(kbh, addr);
                ldsm2(kbl, addr + T_ARR);
                mma16816(s_[nf], qfh[kk], kbh);
                mma16816(s_[nf], qfh[kk], kbl);
                mma16816(s_[nf], qfl[kk], kbh);
            }
        }

        float tm0 = -1e30f, tm1 = -1e30f;
        #pragma unroll
        for (int nf = 0; nf < 8; nf++) {
            tm0 = fmaxf(tm0, fmaxf(s_[nf][0], s_[nf][1]));
            tm1 = fmaxf(tm1, fmaxf(s_[nf][2], s_[nf][3]));
        }
        tm0 = fmaxf(tm0, __shfl_xor_sync(0xffffffffu, tm0, 1));
        tm0 = fmaxf(tm0, __shfl_xor_sync(0xffffffffu, tm0, 2));
        tm1 = fmaxf(tm1, __shfl_xor_sync(0xffffffffu, tm1, 1));
        tm1 = fmaxf(tm1, __shfl_xor_sync(0xffffffffu, tm1, 2));

        const float mn0 = fmaxf(m0, tm0);
        const float mn1 = fmaxf(m1, tm1);
        const float a0 = __expf(m0 - mn0);
        const float a1 = __expf(m1 - mn1);
        m0 = mn0; m1 = mn1;

        float sum0 = 0.f, sum1 = 0.f;
        #pragma unroll
        for (int nf = 0; nf < 8; nf++) {
            s_[nf][0] = __expf(s_[nf][0] - m0);
            s_[nf][1] = __expf(s_[nf][1] - m0);
            s_[nf][2] = __expf(s_[nf][2] - m1);
            s_[nf][3] = __expf(s_[nf][3] - m1);
            sum0 += s_[nf][0] + s_[nf][1];
            sum1 += s_[nf][2] + s_[nf][3];
        }
        sum0 += __shfl_xor_sync(0xffffffffu, sum0, 1);
        sum0 += __shfl_xor_sync(0xffffffffu, sum0, 2);
        sum1 += __shfl_xor_sync(0xffffffffu, sum1, 1);
        sum1 += __shfl_xor_sync(0xffffffffu, sum1, 2);
        l0 = l0 * a0 + sum0;
        l1 = l1 * a1 + sum1;

        #pragma unroll
        for (int nf = 0; nf < 8; nf++) {
            o[nf][0] *= a0; o[nf][1] *= a0;
            o[nf][2] *= a1; o[nf][3] *= a1;
        }

        uint32_t pa[4][4];
        #pragma unroll
        for (int kk = 0; kk < 4; kk++) {
            const int n0 = 2 * kk, n1 = 2 * kk + 1;
            pa[kk][0] = pack_h2(s_[n0][0], s_[n0][1]);
            pa[kk][1] = pack_h2(s_[n0][2], s_[n0][3]);
            pa[kk][2] = pack_h2(s_[n1][0], s_[n1][1]);
            pa[kk][3] = pack_h2(s_[n1][2], s_[n1][3]);
        }

        #pragma unroll
        for (int nf = 0; nf < 8; nf++) {
            #pragma unroll
            for (int kk = 0; kk < 4; kk++) {
                uint32_t vb[2];
                ldsm2(vb, base_v + bo + nf * 8 * AROW + kk * 32);
                mma16816h(o[nf], pa[kk], vb);
            }
        }

        if (++st == 3) st = 0;
    }

    const float inv0 = 1.f / l0;
    const float inv1 = 1.f / l1;
    const int b = bh >> 4;
    const int h = bh & 15;
    const int r0 = qb * 128 + wid * 16 + (lane >> 2);
    const size_t tok0 = (size_t)(b * S_LEN + r0) * D_MODEL;
    const size_t tok1 = (size_t)(b * S_LEN + r0 + 8) * D_MODEL;
    #pragma unroll
    for (int nf = 0; nf < 8; nf++) {
        const int col = h * HEAD_D + nf * 8 + (lane & 3) * 2;
        uint32_t hi, lo;
        split2_pack(o[nf][0] * inv0, o[nf][1] * inv0, hi, lo);
        *(uint32_t*)(outh + tok0 + col) = hi;
        *(uint32_t*)(outl + tok0 + col) = lo;
        split2_pack(o[nf][2] * inv1, o[nf][3] * inv1, hi, lo);
        *(uint32_t*)(outh + tok1 + col) = hi;
        *(uint32_t*)(outl + tok1 + col) = lo;
    }
}

// ---------------------------------------------------------------------------
extern "C" void kernel_launch(void* const* d_in, const int* in_sizes, int n_in,
                              void* d_out, int out_size)
{
    const float* x     = (const float*)d_in[0];
    const float* w_qkv = (const float*)d_in[1];
    const float* b_qkv = (const float*)d_in[2];
    const float* w_o   = (const float*)d_in[3];
    const float* b_o   = (const float*)d_in[4];
    float* out = (float*)d_out;

    float* qkv;
    __nv_bfloat16 *xh, *xl, *wqh, *wql, *woh, *wol, *ath, *atl;
    __nv_bfloat16 *pqh, *pql, *pkh, *pkl;
    __half* pvt;
    cudaGetSymbolAddress((void**)&qkv, g_qkv);
    cudaGetSymbolAddress((void**)&xh,  g_x_hi);  cudaGetSymbolAddress((void**)&xl,  g_x_lo);
    cudaGetSymbolAddress((void**)&wqh, g_wq_hi); cudaGetSymbolAddress((void**)&wql, g_wq_lo);
    cudaGetSymbolAddress((void**)&woh, g_wo_hi); cudaGetSymbolAddress((void**)&wol, g_wo_lo);
    cudaGetSymbolAddress((void**)&ath, g_at_hi); cudaGetSymbolAddress((void**)&atl, g_at_lo);
    cudaGetSymbolAddress((void**)&pqh, g_q_hi);  cudaGetSymbolAddress((void**)&pql, g_q_lo);
    cudaGetSymbolAddress((void**)&pkh, g_k_hi);  cudaGetSymbolAddress((void**)&pkl, g_k_lo);
    cudaGetSymbolAddress((void**)&pvt, g_vt);

    cudaFuncSetAttribute(gemm_hmma, cudaFuncAttributeMaxDynamicSharedMemorySize, GEMM_SMEM);
    cudaFuncSetAttribute(attn_mma,  cudaFuncAttributeMaxDynamicSharedMemorySize, ATTN_SMEM);

    // input splits
    {
        int n4 = M_ROWS * KDIM / 4;
        split_kernel<<<(n4 + 255) / 256, 256>>>((const float4*)x,
            (__nv_bfloat162*)xh, (__nv_bfloat162*)xl, n4);
    }
    {
        int n4 = TDQ * KDIM / 4;
        split_kernel<<<(n4 + 255) / 256, 256>>>((const float4*)w_qkv,
            (__nv_bfloat162*)wqh, (__nv_bfloat162*)wql, n4);
    }
    {
        int n4 = D_MODEL * KDIM / 4;
        split_kernel<<<(n4 + 255) / 256, 256>>>((const float4*)w_o,
            (__nv_bfloat162*)woh, (__nv_bfloat162*)wol, n4);
    }

    // 1) QKV projection
    {
        dim3 grid(TDQ / 256, M_ROWS / 128);
        gemm_hmma<<<grid, 256, GEMM_SMEM>>>(xh, xl, wqh, wql, b_qkv, qkv,
                                            M_ROWS, TDQ, KDIM);
    }
    // 2) prep attention planes
    {
        dim3 grid(S_LEN / 256, BH);
        prep_qkv<<<grid, 256>>>(qkv, pqh, pql, pkh, pkl, pvt);
    }
    // 3) tensor-core flash attention
    {
        dim3 grid(S_LEN / 128, BH);
        attn_mma<<<grid, 256, ATTN_SMEM>>>(pqh, pql, pkh, pkl, pvt, ath, atl);
    }
    // 4) output projection
    {
        dim3 grid(D_MODEL / 256, M_ROWS / 128);
        gemm_hmma<<<grid, 256, GEMM_SMEM>>>(ath, atl, woh, wol, b_o, out,
                                            M_ROWS, D_MODEL, KDIM);
    }
}

// round 7
// speedup vs baseline: 2.2829x; 2.2829x over previous
#include <cuda_runtime.h>
#include <cuda_fp16.h>
#include <cstdint>
#include <cstddef>

// Problem constants
#define BATCH   4
#define S_LEN   2048
#define D_MODEL 1024
#define NHEAD   16
#define HEAD_D  64
#define TDQ     (3 * D_MODEL)          // 3072
#define M_ROWS  (BATCH * S_LEN)        // 8192
#define KDIM    D_MODEL                // 1024
#define BH      (BATCH * NHEAD)        // 64

// ---------------------------------------------------------------------------
// Scratch (__device__ globals; allocation-free rule)
// ---------------------------------------------------------------------------
__device__ __align__(128) __half g_x16  [(size_t)M_ROWS * KDIM];
__device__ __align__(128) __half g_wq16 [(size_t)TDQ    * KDIM];
__device__ __align__(128) __half g_wo16 [(size_t)D_MODEL* KDIM];
__device__ __align__(128) __half g_qkv16[(size_t)M_ROWS * TDQ];
__device__ __align__(128) __half g_at16 [(size_t)M_ROWS * D_MODEL];
__device__ __align__(128) __half g_q16  [(size_t)BH * S_LEN * HEAD_D];
__device__ __align__(128) __half g_k16  [(size_t)BH * S_LEN * HEAD_D];
__device__ __align__(128) __half g_vt16 [(size_t)BH * HEAD_D * S_LEN];

// ---------------------------------------------------------------------------
// Helpers
// ---------------------------------------------------------------------------
__device__ __forceinline__ uint32_t smem_u32(const void* p) {
    uint32_t a;
    asm("{ .reg .u64 t; cvta.to.shared.u64 t, %1; cvt.u32.u64 %0, t; }"
        : "=r"(a) : "l"(p));
    return a;
}

#define CP_ASYNC16(saddr, gptr) \
    asm volatile("cp.async.cg.shared.global [%0], [%1], 16;" :: "r"(saddr), "l"(gptr))
#define CP_COMMIT() asm volatile("cp.async.commit_group;" ::: "memory")
#define CP_WAIT0()  asm volatile("cp.async.wait_group 0;" ::: "memory")
#define CP_WAIT1()  asm volatile("cp.async.wait_group 1;" ::: "memory")

__device__ __forceinline__ void ldsm4(uint32_t* r, uint32_t addr) {
    asm volatile("ldmatrix.sync.aligned.m8n8.x4.shared.b16 {%0,%1,%2,%3}, [%4];"
                 : "=r"(r[0]), "=r"(r[1]), "=r"(r[2]), "=r"(r[3]) : "r"(addr));
}
__device__ __forceinline__ void ldsm2(uint32_t* r, uint32_t addr) {
    asm volatile("ldmatrix.sync.aligned.m8n8.x2.shared.b16 {%0,%1}, [%2];"
                 : "=r"(r[0]), "=r"(r[1]) : "r"(addr));
}
__device__ __forceinline__ void mma16816h(float* d, const uint32_t* a, const uint32_t* b) {
    asm volatile(
        "mma.sync.aligned.m16n8k16.row.col.f32.f16.f16.f32 "
        "{%0,%1,%2,%3}, {%4,%5,%6,%7}, {%8,%9}, {%0,%1,%2,%3};"
        : "+f"(d[0]), "+f"(d[1]), "+f"(d[2]), "+f"(d[3])
        : "r"(a[0]), "r"(a[1]), "r"(a[2]), "r"(a[3]), "r"(b[0]), "r"(b[1]));
}
__device__ __forceinline__ uint32_t pack_h2(float x, float y) {
    __half2 h = __floats2half2_rn(x, y);
    return *(uint32_t*)&h;
}

// ---------------------------------------------------------------------------
// fp32 -> fp16 convert
// ---------------------------------------------------------------------------
__global__ void __launch_bounds__(256)
cvt16(const float4* __restrict__ src, uint2* __restrict__ dst, int n4)
{
    int i = blockIdx.x * blockDim.x + threadIdx.x;
    if (i >= n4) return;
    float4 v = src[i];
    uint2 o;
    o.x = pack_h2(v.x, v.y);
    o.y = pack_h2(v.z, v.w);
    dst[i] = o;
}

// ---------------------------------------------------------------------------
// fp16 HMMA GEMM (NT): C[m,n] = sum_k A[m,k]*B[n,k] + bias[n]
// 128(M) x 256(N) CTA tile, BK=32, 8 warps 2(M)x4(N), 64x64 warp tile.
// 3-stage cp.async pipeline. half_out: C is fp16, else fp32.
// ---------------------------------------------------------------------------
#define ROWB   80
#define A_ARR  (128 * ROWB)             // 10240
#define B_ARR  (256 * ROWB)             // 20480
#define STAGE_B (A_ARR + B_ARR)         // 30720
#define GEMM_SMEM (3 * STAGE_B)         // 92160

__global__ void __launch_bounds__(256, 1)
gemm_hmma(const __half* __restrict__ A, const __half* __restrict__ B,
          const float* __restrict__ bias, void* __restrict__ Cv,
          int M, int N, int K, int half_out)
{
    extern __shared__ char sm[];
    const int tid  = threadIdx.x;
    const int wid  = tid >> 5;
    const int lane = tid & 31;
    const int wm   = wid & 1;           // 0..1 (M)
    const int wn   = wid >> 1;          // 0..3 (N)
    const int row0 = blockIdx.y * 128;
    const int col0 = blockIdx.x * 256;

    const uint32_t smb = smem_u32(sm);
    const int lr = tid >> 2;            // 0..63
    const int lc = tid & 3;             // 16B chunk (BK=32 fp16 = 64B = 4 chunks)

    auto ld_chunk = [&](int i, int stage) {
        const int k0 = i * 32;
        uint32_t sb = smb + stage * STAGE_B;
        #pragma unroll
        for (int rep = 0; rep < 2; rep++) {
            int rr = lr + rep * 64;
            size_t go = (size_t)(row0 + rr) * K + k0 + lc * 8;
            CP_ASYNC16(sb + rr * ROWB + lc * 16, A + go);
        }
        #pragma unroll
        for (int rep = 0; rep < 4; rep++) {
            int rr = lr + rep * 64;
            size_t go = (size_t)(col0 + rr) * K + k0 + lc * 8;
            CP_ASYNC16(sb + A_ARR + rr * ROWB + lc * 16, B + go);
        }
    };

    float acc[4][8][4];
    #pragma unroll
    for (int i = 0; i < 4; i++)
        #pragma unroll
        for (int j = 0; j < 8; j++)
            #pragma unroll
            for (int v = 0; v < 4; v++) acc[i][j][v] = 0.f;

    const int arow = (lane & 7) + ((lane >> 3) & 1) * 8;
    const int akb  = (lane >> 4) * 16;
    const uint32_t aoff = (uint32_t)((wm * 64 + arow) * ROWB + akb);
    const uint32_t boff = (uint32_t)((wn * 64 + (lane & 7)) * ROWB + ((lane >> 3) & 1) * 16);

    const int NC = K / 32;
    ld_chunk(0, 0); CP_COMMIT();
    ld_chunk(1, 1); CP_COMMIT();

    int st = 0;
    for (int i = 0; i < NC; i++) {
        if (i < NC - 1) { CP_WAIT1(); } else { CP_WAIT0(); }
        __syncthreads();
        if (i + 2 < NC) {
            int s2 = st + 2; if (s2 >= 3) s2 -= 3;
            ld_chunk(i + 2, s2);
            CP_COMMIT();
        }

        const uint32_t sA = smb + st * STAGE_B;
        const uint32_t sB = sA + A_ARR;

        #pragma unroll
        for (int ks = 0; ks < 2; ks++) {
            uint32_t ah[4][4], bh[8][2];
            #pragma unroll
            for (int fi = 0; fi < 4; fi++)
                ldsm4(ah[fi], sA + aoff + fi * 16 * ROWB + ks * 32);
            #pragma unroll
            for (int fj = 0; fj < 8; fj++)
                ldsm2(bh[fj], sB + boff + fj * 8 * ROWB + ks * 32);
            #pragma unroll
            for (int fi = 0; fi < 4; fi++)
                #pragma unroll
                for (int fj = 0; fj < 8; fj++)
                    mma16816h(acc[fi][fj], ah[fi], bh[fj]);
        }
        if (++st == 3) st = 0;
    }

    if (half_out) {
        __half* C = (__half*)Cv;
        #pragma unroll
        for (int fi = 0; fi < 4; fi++) {
            const int r = row0 + wm * 64 + fi * 16 + (lane >> 2);
            #pragma unroll
            for (int fj = 0; fj < 8; fj++) {
                const int cc = col0 + wn * 64 + fj * 8 + (lane & 3) * 2;
                float2 bb = *(const float2*)&bias[cc];
                *(uint32_t*)&C[(size_t)r * N + cc] =
                    pack_h2(acc[fi][fj][0] + bb.x, acc[fi][fj][1] + bb.y);
                *(uint32_t*)&C[(size_t)(r + 8) * N + cc] =
                    pack_h2(acc[fi][fj][2] + bb.x, acc[fi][fj][3] + bb.y);
            }
        }
    } else {
        float* C = (float*)Cv;
        #pragma unroll
        for (int fi = 0; fi < 4; fi++) {
            const int r = row0 + wm * 64 + fi * 16 + (lane >> 2);
            #pragma unroll
            for (int fj = 0; fj < 8; fj++) {
                const int cc = col0 + wn * 64 + fj * 8 + (lane & 3) * 2;
                float2 bb = *(const float2*)&bias[cc];
                float2 v0 = make_float2(acc[fi][fj][0] + bb.x, acc[fi][fj][1] + bb.y);
                float2 v1 = make_float2(acc[fi][fj][2] + bb.x, acc[fi][fj][3] + bb.y);
                *(float2*)&C[(size_t)r * N + cc]       = v0;
                *(float2*)&C[(size_t)(r + 8) * N + cc] = v1;
            }
        }
    }
}

// ---------------------------------------------------------------------------
// Prep: qkv fp16 [token][3072] -> Q fp16 (scaled 1/8) [bh][s][64],
//       K fp16 [bh][s][64], V^T fp16 [bh][d][s]. Pure data movement.
// ---------------------------------------------------------------------------
__global__ void __launch_bounds__(256)
prep_qkv(const __half* __restrict__ qkv,
         __half* __restrict__ q, __half* __restrict__ k, __half* __restrict__ vt)
{
    const int s  = blockIdx.x * 256 + threadIdx.x;
    const int bh = blockIdx.y;
    const int b  = bh >> 4;
    const int h  = bh & 15;
    const __half* src = qkv + ((size_t)(b * S_LEN + s)) * TDQ + h * 3 * HEAD_D;

    __half* qp = q + ((size_t)bh * S_LEN + s) * HEAD_D;
    __half* kp = k + ((size_t)bh * S_LEN + s) * HEAD_D;

    const __half2 sc = __half2half2(__float2half(0.125f));   // exact power of 2
    #pragma unroll
    for (int j = 0; j < 8; j++) {
        uint4 tq = ((const uint4*)src)[j];
        __half2* hq = (__half2*)&tq;
        hq[0] = __hmul2(hq[0], sc); hq[1] = __hmul2(hq[1], sc);
        hq[2] = __hmul2(hq[2], sc); hq[3] = __hmul2(hq[3], sc);
        ((uint4*)qp)[j] = tq;
        ((uint4*)kp)[j] = ((const uint4*)(src + HEAD_D))[j];
    }
    const __half* vsrc = src + 2 * HEAD_D;
    #pragma unroll
    for (int d = 0; d < HEAD_D; d++)
        vt[((size_t)bh * HEAD_D + d) * S_LEN + s] = vsrc[d];
}

// ---------------------------------------------------------------------------
// Flash attention, fp16 HMMA single-pass. 128 q rows/CTA, 8 warps x 16 rows,
// 64-key tiles, 3-stage cp.async pipeline, 2 CTAs/SM.
// ---------------------------------------------------------------------------
#define AROW     144
#define Q_ARR    (128 * AROW)          // 18432
#define T_ARR    (64 * AROW)           // 9216
#define T_STAGE  (2 * T_ARR)           // 18432 (K, V)
#define ATTN_SMEM (Q_ARR + 3 * T_STAGE)   // 73728

__global__ void __launch_bounds__(256, 2)
attn_mma(const __half* __restrict__ q, const __half* __restrict__ k,
         const __half* __restrict__ vt, __half* __restrict__ outp)
{
    extern __shared__ char sm[];
    const uint32_t smb = smem_u32(sm);
    const int tid  = threadIdx.x;
    const int wid  = tid >> 5;
    const int lane = tid & 31;
    const int bh = blockIdx.y;
    const int qb = blockIdx.x;

    const __half* Qp = q  + ((size_t)bh * S_LEN + qb * 128) * HEAD_D;
    const __half* Kp = k  + (size_t)bh * S_LEN * HEAD_D;
    const __half* Vt = vt + (size_t)bh * HEAD_D * S_LEN;

    auto ld_tile = [&](int kt, int st) {
        const int k0 = kt * 64;
        const uint32_t sb = smb + Q_ARR + st * T_STAGE;
        #pragma unroll
        for (int rep = 0; rep < 2; rep++) {
            int idx = tid + rep * 256;        // 0..511
            int row = idx >> 3;               // 0..63
            int ch  = idx & 7;
            uint32_t so = row * AROW + ch * 16;
            CP_ASYNC16(sb +         so, Kp + (size_t)(k0 + row) * HEAD_D + ch * 8);
            CP_ASYNC16(sb + T_ARR + so, Vt + (size_t)row * S_LEN + k0 + ch * 8);
        }
    };

    // group 0: Q + tile 0; group 1: tile 1
    #pragma unroll
    for (int rep = 0; rep < 4; rep++) {
        int idx = tid + rep * 256;
        int row = idx >> 3;
        int ch  = idx & 7;
        CP_ASYNC16(smb + row * AROW + ch * 16, Qp + (size_t)row * HEAD_D + ch * 8);
    }
    ld_tile(0, 0);
    CP_COMMIT();
    ld_tile(1, 1);
    CP_COMMIT();

    CP_WAIT1();
    __syncthreads();
    const int arow = (lane & 7) + ((lane >> 3) & 1) * 8;
    const int akb  = (lane >> 4) * 16;
    const uint32_t qbase = smb + (uint32_t)((wid * 16 + arow) * AROW + akb);
    uint32_t qf[4][4];
    #pragma unroll
    for (int kk = 0; kk < 4; kk++) ldsm4(qf[kk], qbase + kk * 32);

    float o[8][4];
    #pragma unroll
    for (int nf = 0; nf < 8; nf++)
        #pragma unroll
        for (int v = 0; v < 4; v++) o[nf][v] = 0.f;
    float m0 = -1e30f, m1 = -1e30f, l0 = 0.f, l1 = 0.f;

    const uint32_t bo = (uint32_t)((lane & 7) * AROW + ((lane >> 3) & 1) * 16);
    const int NT = S_LEN / 64;

    int st = 0;
    for (int kt = 0; kt < NT; kt++) {
        if (kt < NT - 1) { CP_WAIT1(); } else { CP_WAIT0(); }
        __syncthreads();
        if (kt + 2 < NT) {
            int s2 = st + 2; if (s2 >= 3) s2 -= 3;
            ld_tile(kt + 2, s2);
            CP_COMMIT();
        }

        const uint32_t base_k = smb + Q_ARR + st * T_STAGE;
        const uint32_t base_v = base_k + T_ARR;

        float s_[8][4];
        #pragma unroll
        for (int nf = 0; nf < 8; nf++)
            #pragma unroll
            for (int v = 0; v < 4; v++) s_[nf][v] = 0.f;

        #pragma unroll
        for (int nf = 0; nf < 8; nf++) {
            #pragma unroll
            for (int kk = 0; kk < 4; kk++) {
                uint32_t kb[2];
                ldsm2(kb, base_k + bo + nf * 8 * AROW + kk * 32);
                mma16816h(s_[nf], qf[kk], kb);
            }
        }

        float tm0 = -1e30f, tm1 = -1e30f;
        #pragma unroll
        for (int nf = 0; nf < 8; nf++) {
            tm0 = fmaxf(tm0, fmaxf(s_[nf][0], s_[nf][1]));
            tm1 = fmaxf(tm1, fmaxf(s_[nf][2], s_[nf][3]));
        }
        tm0 = fmaxf(tm0, __shfl_xor_sync(0xffffffffu, tm0, 1));
        tm0 = fmaxf(tm0, __shfl_xor_sync(0xffffffffu, tm0, 2));
        tm1 = fmaxf(tm1, __shfl_xor_sync(0xffffffffu, tm1, 1));
        tm1 = fmaxf(tm1, __shfl_xor_sync(0xffffffffu, tm1, 2));

        const float mn0 = fmaxf(m0, tm0);
        const float mn1 = fmaxf(m1, tm1);
        const float a0 = __expf(m0 - mn0);
        const float a1 = __expf(m1 - mn1);
        m0 = mn0; m1 = mn1;

        float sum0 = 0.f, sum1 = 0.f;
        #pragma unroll
        for (int nf = 0; nf < 8; nf++) {
            s_[nf][0] = __expf(s_[nf][0] - m0);
            s_[nf][1] = __expf(s_[nf][1] - m0);
            s_[nf][2] = __expf(s_[nf][2] - m1);
            s_[nf][3] = __expf(s_[nf][3] - m1);
            sum0 += s_[nf][0] + s_[nf][1];
            sum1 += s_[nf][2] + s_[nf][3];
        }
        sum0 += __shfl_xor_sync(0xffffffffu, sum0, 1);
        sum0 += __shfl_xor_sync(0xffffffffu, sum0, 2);
        sum1 += __shfl_xor_sync(0xffffffffu, sum1, 1);
        sum1 += __shfl_xor_sync(0xffffffffu, sum1, 2);
        l0 = l0 * a0 + sum0;
        l1 = l1 * a1 + sum1;

        #pragma unroll
        for (int nf = 0; nf < 8; nf++) {
            o[nf][0] *= a0; o[nf][1] *= a0;
            o[nf][2] *= a1; o[nf][3] *= a1;
        }

        uint32_t pa[4][4];
        #pragma unroll
        for (int kk = 0; kk < 4; kk++) {
            const int n0 = 2 * kk, n1 = 2 * kk + 1;
            pa[kk][0] = pack_h2(s_[n0][0], s_[n0][1]);
            pa[kk][1] = pack_h2(s_[n0][2], s_[n0][3]);
            pa[kk][2] = pack_h2(s_[n1][0], s_[n1][1]);
            pa[kk][3] = pack_h2(s_[n1][2], s_[n1][3]);
        }

        #pragma unroll
        for (int nf = 0; nf < 8; nf++) {
            #pragma unroll
            for (int kk = 0; kk < 4; kk++) {
                uint32_t vb[2];
                ldsm2(vb, base_v + bo + nf * 8 * AROW + kk * 32);
                mma16816h(o[nf], pa[kk], vb);
            }
        }

        if (++st == 3) st = 0;
    }

    const float inv0 = 1.f / l0;
    const float inv1 = 1.f / l1;
    const int b = bh >> 4;
    const int h = bh & 15;
    const int r0 = qb * 128 + wid * 16 + (lane >> 2);
    const size_t tok0 = (size_t)(b * S_LEN + r0) * D_MODEL;
    const size_t tok1 = (size_t)(b * S_LEN + r0 + 8) * D_MODEL;
    #pragma unroll
    for (int nf = 0; nf < 8; nf++) {
        const int col = h * HEAD_D + nf * 8 + (lane & 3) * 2;
        *(uint32_t*)(outp + tok0 + col) = pack_h2(o[nf][0] * inv0, o[nf][1] * inv0);
        *(uint32_t*)(outp + tok1 + col) = pack_h2(o[nf][2] * inv1, o[nf][3] * inv1);
    }
}

// ---------------------------------------------------------------------------
extern "C" void kernel_launch(void* const* d_in, const int* in_sizes, int n_in,
                              void* d_out, int out_size)
{
    const float* x     = (const float*)d_in[0];
    const float* w_qkv = (const float*)d_in[1];
    const float* b_qkv = (const float*)d_in[2];
    const float* w_o   = (const float*)d_in[3];
    const float* b_o   = (const float*)d_in[4];
    float* out = (float*)d_out;

    __half *x16, *wq16, *wo16, *qkv16, *at16, *q16, *k16, *vt16;
    cudaGetSymbolAddress((void**)&x16,   g_x16);
    cudaGetSymbolAddress((void**)&wq16,  g_wq16);
    cudaGetSymbolAddress((void**)&wo16,  g_wo16);
    cudaGetSymbolAddress((void**)&qkv16, g_qkv16);
    cudaGetSymbolAddress((void**)&at16,  g_at16);
    cudaGetSymbolAddress((void**)&q16,   g_q16);
    cudaGetSymbolAddress((void**)&k16,   g_k16);
    cudaGetSymbolAddress((void**)&vt16,  g_vt16);

    cudaFuncSetAttribute(gemm_hmma, cudaFuncAttributeMaxDynamicSharedMemorySize, GEMM_SMEM);
    cudaFuncSetAttribute(attn_mma,  cudaFuncAttributeMaxDynamicSharedMemorySize, ATTN_SMEM);

    // fp32 -> fp16 converts
    {
        int n4 = M_ROWS * KDIM / 4;
        cvt16<<<(n4 + 255) / 256, 256>>>((const float4*)x, (uint2*)x16, n4);
    }
    {
        int n4 = TDQ * KDIM / 4;
        cvt16<<<(n4 + 255) / 256, 256>>>((const float4*)w_qkv, (uint2*)wq16, n4);
    }
    {
        int n4 = D_MODEL * KDIM / 4;
        cvt16<<<(n4 + 255) / 256, 256>>>((const float4*)w_o, (uint2*)wo16, n4);
    }

    // 1) QKV projection -> fp16
    {
        dim3 grid(TDQ / 256, M_ROWS / 128);
        gemm_hmma<<<grid, 256, GEMM_SMEM>>>(x16, wq16, b_qkv, qkv16,
                                            M_ROWS, TDQ, KDIM, 1);
    }
    // 2) prep attention planes (pure rearrange)
    {
        dim3 grid(S_LEN / 256, BH);
        prep_qkv<<<grid, 256>>>(qkv16, q16, k16, vt16);
    }
    // 3) tensor-core flash attention -> fp16 [token][1024]
    {
        dim3 grid(S_LEN / 128, BH);
        attn_mma<<<grid, 256, ATTN_SMEM>>>(q16, k16, vt16, at16);
    }
    // 4) output projection -> fp32
    {
        dim3 grid(D_MODEL / 256, M_ROWS / 128);
        gemm_hmma<<<grid, 256, GEMM_SMEM>>>(at16, wo16, b_o, out,
                                            M_ROWS, D_MODEL, KDIM, 0);
    }
}

// round 9
// speedup vs baseline: 2.5942x; 1.1364x over previous
#include <cuda_runtime.h>
#include <cuda_fp16.h>
#include <cstdint>
#include <cstddef>

// Problem constants
#define BATCH   4
#define S_LEN   2048
#define D_MODEL 1024
#define NHEAD   16
#define HEAD_D  64
#define TDQ     (3 * D_MODEL)          // 3072
#define M_ROWS  (BATCH * S_LEN)        // 8192
#define KDIM    D_MODEL                // 1024
#define BH      (BATCH * NHEAD)        // 64

// ---------------------------------------------------------------------------
// Scratch (__device__ globals; allocation-free rule)
// ---------------------------------------------------------------------------
__device__ __align__(128) __half g_x16  [(size_t)M_ROWS * KDIM];
__device__ __align__(128) __half g_wq16 [(size_t)TDQ    * KDIM];
__device__ __align__(128) __half g_wo16 [(size_t)D_MODEL* KDIM];
__device__ __align__(128) __half g_qkv16[(size_t)M_ROWS * TDQ];
__device__ __align__(128) __half g_at16 [(size_t)M_ROWS * D_MODEL];
__device__ __align__(128) __half g_vt16 [(size_t)BH * HEAD_D * S_LEN];

// ---------------------------------------------------------------------------
// Helpers
// ---------------------------------------------------------------------------
__device__ __forceinline__ uint32_t smem_u32(const void* p) {
    uint32_t a;
    asm("{ .reg .u64 t; cvta.to.shared.u64 t, %1; cvt.u32.u64 %0, t; }"
        : "=r"(a) : "l"(p));
    return a;
}

#define CP_ASYNC16(saddr, gptr) \
    asm volatile("cp.async.cg.shared.global [%0], [%1], 16;" :: "r"(saddr), "l"(gptr))
#define CP_COMMIT() asm volatile("cp.async.commit_group;" ::: "memory")
#define CP_WAIT0()  asm volatile("cp.async.wait_group 0;" ::: "memory")
#define CP_WAIT1()  asm volatile("cp.async.wait_group 1;" ::: "memory")

__device__ __forceinline__ void ldsm4(uint32_t* r, uint32_t addr) {
    asm volatile("ldmatrix.sync.aligned.m8n8.x4.shared.b16 {%0,%1,%2,%3}, [%4];"
                 : "=r"(r[0]), "=r"(r[1]), "=r"(r[2]), "=r"(r[3]) : "r"(addr));
}
__device__ __forceinline__ void mma16816h(float* d, const uint32_t* a,
                                          uint32_t b0, uint32_t b1) {
    asm volatile(
        "mma.sync.aligned.m16n8k16.row.col.f32.f16.f16.f32 "
        "{%0,%1,%2,%3}, {%4,%5,%6,%7}, {%8,%9}, {%0,%1,%2,%3};"
        : "+f"(d[0]), "+f"(d[1]), "+f"(d[2]), "+f"(d[3])
        : "r"(a[0]), "r"(a[1]), "r"(a[2]), "r"(a[3]), "r"(b0), "r"(b1));
}
__device__ __forceinline__ uint32_t pack_h2(float x, float y) {
    __half2 h = __floats2half2_rn(x, y);
    return *(uint32_t*)&h;
}

// ---------------------------------------------------------------------------
// fp32 -> fp16 convert
// ---------------------------------------------------------------------------
__global__ void __launch_bounds__(256)
cvt16(const float4* __restrict__ src, uint2* __restrict__ dst, int n4)
{
    int i = blockIdx.x * blockDim.x + threadIdx.x;
    if (i >= n4) return;
    float4 v = src[i];
    uint2 o;
    o.x = pack_h2(v.x, v.y);
    o.y = pack_h2(v.z, v.w);
    dst[i] = o;
}

// ---------------------------------------------------------------------------
// fp16 HMMA GEMM (NT): C[m,n] = sum_k A[m,k]*B[n,k] + bias[n]
// 128(M) x 256(N) CTA tile, BK=64, 8 warps 2(M)x4(N), 64x64 warp tile.
// 3-stage cp.async pipeline, ldsm4 for both operands.
// ---------------------------------------------------------------------------
#define ROWB   144                      // 128B data + 16 pad
#define A_ARR  (128 * ROWB)             // 18432
#define B_ARR  (256 * ROWB)             // 36864
#define STAGE_B (A_ARR + B_ARR)         // 55296
#define GEMM_SMEM (3 * STAGE_B)         // 165888

__global__ void __launch_bounds__(256, 1)
gemm_hmma(const __half* __restrict__ A, const __half* __restrict__ B,
          const float* __restrict__ bias, void* __restrict__ Cv,
          int M, int N, int K, int half_out)
{
    extern __shared__ char sm[];
    const int tid  = threadIdx.x;
    const int wid  = tid >> 5;
    const int lane = tid & 31;
    const int wm   = wid & 1;           // 0..1 (M)
    const int wn   = wid >> 1;          // 0..3 (N)
    const int row0 = blockIdx.y * 128;
    const int col0 = blockIdx.x * 256;

    const uint32_t smb = smem_u32(sm);

    auto ld_chunk = [&](int i, int stage) {
        const int k0 = i * 64;
        uint32_t sb = smb + stage * STAGE_B;
        #pragma unroll
        for (int rep = 0; rep < 4; rep++) {        // A: 128 rows x 8 chunks
            int idx = tid + rep * 256;
            int row = idx >> 3, ch = idx & 7;
            size_t go = (size_t)(row0 + row) * K + k0 + ch * 8;
            CP_ASYNC16(sb + row * ROWB + ch * 16, A + go);
        }
        #pragma unroll
        for (int rep = 0; rep < 8; rep++) {        // B: 256 rows x 8 chunks
            int idx = tid + rep * 256;
            int row = idx >> 3, ch = idx & 7;
            size_t go = (size_t)(col0 + row) * K + k0 + ch * 8;
            CP_ASYNC16(sb + A_ARR + row * ROWB + ch * 16, B + go);
        }
    };

    float acc[4][8][4];
    #pragma unroll
    for (int i = 0; i < 4; i++)
        #pragma unroll
        for (int j = 0; j < 8; j++)
            #pragma unroll
            for (int v = 0; v < 4; v++) acc[i][j][v] = 0.f;

    // x4 lane addressing: row = lane&15, k-half = lane>>4
    const uint32_t aoff = (uint32_t)((wm * 64 + (lane & 15)) * ROWB + (lane >> 4) * 16);
    const uint32_t boff = (uint32_t)((wn * 64 + (lane & 15)) * ROWB + (lane >> 4) * 16);

    const int NC = K / 64;
    ld_chunk(0, 0); CP_COMMIT();
    ld_chunk(1, 1); CP_COMMIT();

    int st = 0;
    for (int i = 0; i < NC; i++) {
        if (i < NC - 1) { CP_WAIT1(); } else { CP_WAIT0(); }
        __syncthreads();
        if (i + 2 < NC) {
            int s2 = st + 2; if (s2 >= 3) s2 -= 3;
            ld_chunk(i + 2, s2);
            CP_COMMIT();
        }

        const uint32_t sA = smb + st * STAGE_B;
        const uint32_t sB = sA + A_ARR;

        #pragma unroll
        for (int ks = 0; ks < 4; ks++) {
            uint32_t ah[4][4], bb[4][4];
            #pragma unroll
            for (int fi = 0; fi < 4; fi++)
                ldsm4(ah[fi], sA + aoff + fi * 16 * ROWB + ks * 32);
            #pragma unroll
            for (int fp = 0; fp < 4; fp++)
                ldsm4(bb[fp], sB + boff + fp * 16 * ROWB + ks * 32);
            #pragma unroll
            for (int fi = 0; fi < 4; fi++)
                #pragma unroll
                for (int fp = 0; fp < 4; fp++) {
                    mma16816h(acc[fi][2 * fp],     ah[fi], bb[fp][0], bb[fp][2]);
                    mma16816h(acc[fi][2 * fp + 1], ah[fi], bb[fp][1], bb[fp][3]);
                }
        }
        if (++st == 3) st = 0;
    }

    if (half_out) {
        __half* C = (__half*)Cv;
        #pragma unroll
        for (int fi = 0; fi < 4; fi++) {
            const int r = row0 + wm * 64 + fi * 16 + (lane >> 2);
            #pragma unroll
            for (int fj = 0; fj < 8; fj++) {
                const int cc = col0 + wn * 64 + fj * 8 + (lane & 3) * 2;
                float2 bbv = *(const float2*)&bias[cc];
                *(uint32_t*)&C[(size_t)r * N + cc] =
                    pack_h2(acc[fi][fj][0] + bbv.x, acc[fi][fj][1] + bbv.y);
                *(uint32_t*)&C[(size_t)(r + 8) * N + cc] =
                    pack_h2(acc[fi][fj][2] + bbv.x, acc[fi][fj][3] + bbv.y);
            }
        }
    } else {
        float* C = (float*)Cv;
        #pragma unroll
        for (int fi = 0; fi < 4; fi++) {
            const int r = row0 + wm * 64 + fi * 16 + (lane >> 2);
            #pragma unroll
            for (int fj = 0; fj < 8; fj++) {
                const int cc = col0 + wn * 64 + fj * 8 + (lane & 3) * 2;
                float2 bbv = *(const float2*)&bias[cc];
                float2 v0 = make_float2(acc[fi][fj][0] + bbv.x, acc[fi][fj][1] + bbv.y);
                float2 v1 = make_float2(acc[fi][fj][2] + bbv.x, acc[fi][fj][3] + bbv.y);
                *(float2*)&C[(size_t)r * N + cc]       = v0;
                *(float2*)&C[(size_t)(r + 8) * N + cc] = v1;
            }
        }
    }
}

// ---------------------------------------------------------------------------
// V transpose: qkv16 [token][3072] V-slice -> vt16 [bh][d][s], via smem tile.
// Block: 64 tokens x 64 dims for one bh. Row stride 72 halves = 144 B
// (16B-aligned so uint4 smem stores are legal).
// ---------------------------------------------------------------------------
__global__ void __launch_bounds__(256)
prep_vt(const __half* __restrict__ qkv, __half* __restrict__ vt)
{
    __shared__ __align__(16) __half t[64][72];   // 144B row stride, 16B aligned

    const int s0 = blockIdx.x * 64;
    const int bh = blockIdx.y;
    const int b  = bh >> 4;
    const int h  = bh & 15;
    const int tid = threadIdx.x;

    // load: thread -> (token tt, 16-dim chunk cc)
    {
        const int tt = tid >> 2;
        const int cc = (tid & 3) * 16;
        const __half* src = qkv + ((size_t)(b * S_LEN + s0 + tt)) * TDQ
                            + h * 3 * HEAD_D + 2 * HEAD_D + cc;
        uint4 v0 = *(const uint4*)(src);
        uint4 v1 = *(const uint4*)(src + 8);
        *(uint4*)&t[tt][cc]     = v0;
        *(uint4*)&t[tt][cc + 8] = v1;
    }
    __syncthreads();

    // store: thread -> (dim d, 16-key chunk)
    {
        const int d  = tid >> 2;
        const int k0 = (tid & 3) * 16;
        union { uint4 q[2]; __half hh[16]; } tmp;
        #pragma unroll
        for (int j = 0; j < 16; j++) tmp.hh[j] = t[k0 + j][d];
        __half* dst = vt + ((size_t)bh * HEAD_D + d) * S_LEN + s0 + k0;
        *(uint4*)(dst)     = tmp.q[0];
        *(uint4*)(dst + 8) = tmp.q[1];
    }
}

// ---------------------------------------------------------------------------
// Flash attention, fp16 HMMA. 128 q rows/CTA, 8 warps x 16 rows, 64-key
// tiles, 3-stage cp.async. Q/K straight from qkv16; V from vt16.
// ---------------------------------------------------------------------------
#define AROW     144
#define Q_ARR    (128 * AROW)          // 18432
#define T_ARR    (64 * AROW)           // 9216
#define T_STAGE  (2 * T_ARR)           // 18432 (K, V)
#define ATTN_SMEM (Q_ARR + 3 * T_STAGE)   // 73728

__global__ void __launch_bounds__(256, 2)
attn_mma(const __half* __restrict__ qkv, const __half* __restrict__ vt,
         __half* __restrict__ outp)
{
    extern __shared__ char sm[];
    const uint32_t smb = smem_u32(sm);
    const int tid  = threadIdx.x;
    const int wid  = tid >> 5;
    const int lane = tid & 31;
    const int bh = blockIdx.y;
    const int qb = blockIdx.x;
    const int b  = bh >> 4;
    const int h  = bh & 15;

    const __half* Qp = qkv + ((size_t)(b * S_LEN + qb * 128)) * TDQ + h * 3 * HEAD_D;
    const __half* Kb = qkv + ((size_t)(b * S_LEN)) * TDQ + h * 3 * HEAD_D + HEAD_D;
    const __half* Vt = vt  + (size_t)bh * HEAD_D * S_LEN;

    auto ld_tile = [&](int kt, int st) {
        const int k0 = kt * 64;
        const uint32_t sb = smb + Q_ARR + st * T_STAGE;
        #pragma unroll
        for (int rep = 0; rep < 2; rep++) {
            int idx = tid + rep * 256;        // 0..511
            int row = idx >> 3;               // 0..63
            int ch  = idx & 7;
            uint32_t so = row * AROW + ch * 16;
            CP_ASYNC16(sb +         so, Kb + (size_t)(k0 + row) * TDQ + ch * 8);
            CP_ASYNC16(sb + T_ARR + so, Vt + (size_t)row * S_LEN + k0 + ch * 8);
        }
    };

    // group 0: Q + tile 0; group 1: tile 1
    #pragma unroll
    for (int rep = 0; rep < 4; rep++) {
        int idx = tid + rep * 256;
        int row = idx >> 3;
        int ch  = idx & 7;
        CP_ASYNC16(smb + row * AROW + ch * 16, Qp + (size_t)row * TDQ + ch * 8);
    }
    ld_tile(0, 0);
    CP_COMMIT();
    ld_tile(1, 1);
    CP_COMMIT();

    CP_WAIT1();
    __syncthreads();

    // Q fragments; scale by 1/8 (exact power of two)
    const uint32_t qbase = smb + (uint32_t)((wid * 16 + (lane & 15)) * AROW
                                            + (lane >> 4) * 16);
    uint32_t qf[4][4];
    const __half2 sc = __half2half2(__float2half(0.125f));
    #pragma unroll
    for (int kk = 0; kk < 4; kk++) {
        ldsm4(qf[kk], qbase + kk * 32);
        #pragma unroll
        for (int r = 0; r < 4; r++) {
            __half2 hv = *(__half2*)&qf[kk][r];
            hv = __hmul2(hv, sc);
            qf[kk][r] = *(uint32_t*)&hv;
        }
    }

    float o[8][4];
    #pragma unroll
    for (int nf = 0; nf < 8; nf++)
        #pragma unroll
        for (int v = 0; v < 4; v++) o[nf][v] = 0.f;
    float m0 = -1e30f, m1 = -1e30f, l0 = 0.f, l1 = 0.f;

    const uint32_t bo = (uint32_t)((lane & 15) * AROW + (lane >> 4) * 16);
    const int NT = S_LEN / 64;

    int st = 0;
    for (int kt = 0; kt < NT; kt++) {
        if (kt < NT - 1) { CP_WAIT1(); } else { CP_WAIT0(); }
        __syncthreads();
        if (kt + 2 < NT) {
            int s2 = st + 2; if (s2 >= 3) s2 -= 3;
            ld_tile(kt + 2, s2);
            CP_COMMIT();
        }

        const uint32_t base_k = smb + Q_ARR + st * T_STAGE;
        const uint32_t base_v = base_k + T_ARR;

        float s_[8][4];
        #pragma unroll
        for (int nf = 0; nf < 8; nf++)
            #pragma unroll
            for (int v = 0; v < 4; v++) s_[nf][v] = 0.f;

        // S = Q K^T : K tile rows = keys (n), cols = dims (k)
        #pragma unroll
        for (int np = 0; np < 4; np++) {
            #pragma unroll
            for (int kk = 0; kk < 4; kk++) {
                uint32_t kb[4];
                ldsm4(kb, base_k + bo + np * 16 * AROW + kk * 32);
                mma16816h(s_[2 * np],     qf[kk], kb[0], kb[2]);
                mma16816h(s_[2 * np + 1], qf[kk], kb[1], kb[3]);
            }
        }

        float tm0 = -1e30f, tm1 = -1e30f;
        #pragma unroll
        for (int nf = 0; nf < 8; nf++) {
            tm0 = fmaxf(tm0, fmaxf(s_[nf][0], s_[nf][1]));
            tm1 = fmaxf(tm1, fmaxf(s_[nf][2], s_[nf][3]));
        }
        tm0 = fmaxf(tm0, __shfl_xor_sync(0xffffffffu, tm0, 1));
        tm0 = fmaxf(tm0, __shfl_xor_sync(0xffffffffu, tm0, 2));
        tm1 = fmaxf(tm1, __shfl_xor_sync(0xffffffffu, tm1, 1));
        tm1 = fmaxf(tm1, __shfl_xor_sync(0xffffffffu, tm1, 2));

        const float mn0 = fmaxf(m0, tm0);
        const float mn1 = fmaxf(m1, tm1);
        const float a0 = __expf(m0 - mn0);
        const float a1 = __expf(m1 - mn1);
        m0 = mn0; m1 = mn1;

        float sum0 = 0.f, sum1 = 0.f;
        #pragma unroll
        for (int nf = 0; nf < 8; nf++) {
            s_[nf][0] = __expf(s_[nf][0] - m0);
            s_[nf][1] = __expf(s_[nf][1] - m0);
            s_[nf][2] = __expf(s_[nf][2] - m1);
            s_[nf][3] = __expf(s_[nf][3] - m1);
            sum0 += s_[nf][0] + s_[nf][1];
            sum1 += s_[nf][2] + s_[nf][3];
        }
        sum0 += __shfl_xor_sync(0xffffffffu, sum0, 1);
        sum0 += __shfl_xor_sync(0xffffffffu, sum0, 2);
        sum1 += __shfl_xor_sync(0xffffffffu, sum1, 1);
        sum1 += __shfl_xor_sync(0xffffffffu, sum1, 2);
        l0 = l0 * a0 + sum0;
        l1 = l1 * a1 + sum1;

        #pragma unroll
        for (int nf = 0; nf < 8; nf++) {
            o[nf][0] *= a0; o[nf][1] *= a0;
            o[nf][2] *= a1; o[nf][3] *= a1;
        }

        uint32_t pa[4][4];
        #pragma unroll
        for (int kk = 0; kk < 4; kk++) {
            const int n0 = 2 * kk, n1 = 2 * kk + 1;
            pa[kk][0] = pack_h2(s_[n0][0], s_[n0][1]);
            pa[kk][1] = pack_h2(s_[n0][2], s_[n0][3]);
            pa[kk][2] = pack_h2(s_[n1][0], s_[n1][1]);
            pa[kk][3] = pack_h2(s_[n1][2], s_[n1][3]);
        }

        // O += P V : V^T tile rows = dims (n), cols = keys (k)
        #pragma unroll
        for (int np = 0; np < 4; np++) {
            #pragma unroll
            for (int kk = 0; kk < 4; kk++) {
                uint32_t vb[4];
                ldsm4(vb, base_v + bo + np * 16 * AROW + kk * 32);
                mma16816h(o[2 * np],     pa[kk], vb[0], vb[2]);
                mma16816h(o[2 * np + 1], pa[kk], vb[1], vb[3]);
            }
        }

        if (++st == 3) st = 0;
    }

    const float inv0 = 1.f / l0;
    const float inv1 = 1.f / l1;
    const int r0 = qb * 128 + wid * 16 + (lane >> 2);
    const size_t tok0 = (size_t)(b * S_LEN + r0) * D_MODEL;
    const size_t tok1 = (size_t)(b * S_LEN + r0 + 8) * D_MODEL;
    #pragma unroll
    for (int nf = 0; nf < 8; nf++) {
        const int col = h * HEAD_D + nf * 8 + (lane & 3) * 2;
        *(uint32_t*)(outp + tok0 + col) = pack_h2(o[nf][0] * inv0, o[nf][1] * inv0);
        *(uint32_t*)(outp + tok1 + col) = pack_h2(o[nf][2] * inv1, o[nf][3] * inv1);
    }
}

// ---------------------------------------------------------------------------
extern "C" void kernel_launch(void* const* d_in, const int* in_sizes, int n_in,
                              void* d_out, int out_size)
{
    const float* x     = (const float*)d_in[0];
    const float* w_qkv = (const float*)d_in[1];
    const float* b_qkv = (const float*)d_in[2];
    const float* w_o   = (const float*)d_in[3];
    const float* b_o   = (const float*)d_in[4];
    float* out = (float*)d_out;

    __half *x16, *wq16, *wo16, *qkv16, *at16, *vt16;
    cudaGetSymbolAddress((void**)&x16,   g_x16);
    cudaGetSymbolAddress((void**)&wq16,  g_wq16);
    cudaGetSymbolAddress((void**)&wo16,  g_wo16);
    cudaGetSymbolAddress((void**)&qkv16, g_qkv16);
    cudaGetSymbolAddress((void**)&at16,  g_at16);
    cudaGetSymbolAddress((void**)&vt16,  g_vt16);

    cudaFuncSetAttribute(gemm_hmma, cudaFuncAttributeMaxDynamicSharedMemorySize, GEMM_SMEM);
    cudaFuncSetAttribute(attn_mma,  cudaFuncAttributeMaxDynamicSharedMemorySize, ATTN_SMEM);

    // fp32 -> fp16 converts
    {
        int n4 = M_ROWS * KDIM / 4;
        cvt16<<<(n4 + 255) / 256, 256>>>((const float4*)x, (uint2*)x16, n4);
    }
    {
        int n4 = TDQ * KDIM / 4;
        cvt16<<<(n4 + 255) / 256, 256>>>((const float4*)w_qkv, (uint2*)wq16, n4);
    }
    {
        int n4 = D_MODEL * KDIM / 4;
        cvt16<<<(n4 + 255) / 256, 256>>>((const float4*)w_o, (uint2*)wo16, n4);
    }

    // 1) QKV projection -> fp16
    {
        dim3 grid(TDQ / 256, M_ROWS / 128);
        gemm_hmma<<<grid, 256, GEMM_SMEM>>>(x16, wq16, b_qkv, qkv16,
                                            M_ROWS, TDQ, KDIM, 1);
    }
    // 2) V transpose only
    {
        dim3 grid(S_LEN / 64, BH);
        prep_vt<<<grid, 256>>>(qkv16, vt16);
    }
    // 3) tensor-core flash attention -> fp16 [token][1024]
    {
        dim3 grid(S_LEN / 128, BH);
        attn_mma<<<grid, 256, ATTN_SMEM>>>(qkv16, vt16, at16);
    }
    // 4) output projection -> fp32
    {
        dim3 grid(D_MODEL / 256, M_ROWS / 128);
        gemm_hmma<<<grid, 256, GEMM_SMEM>>>(at16, wo16, b_o, out,
                                            M_ROWS, D_MODEL, KDIM, 0);
    }
}

// round 10
// speedup vs baseline: 2.6410x; 1.0180x over previous
#include <cuda_runtime.h>
#include <cuda_fp16.h>
#include <cstdint>
#include <cstddef>

// Problem constants
#define BATCH   4
#define S_LEN   2048
#define D_MODEL 1024
#define NHEAD   16
#define HEAD_D  64
#define TDQ     (3 * D_MODEL)          // 3072
#define M_ROWS  (BATCH * S_LEN)        // 8192
#define KDIM    D_MODEL                // 1024
#define BH      (BATCH * NHEAD)        // 64

// ---------------------------------------------------------------------------
// Scratch (__device__ globals; allocation-free rule)
// ---------------------------------------------------------------------------
__device__ __align__(128) __half g_x16  [(size_t)M_ROWS * KDIM];
__device__ __align__(128) __half g_wq16 [(size_t)TDQ    * KDIM];
__device__ __align__(128) __half g_wo16 [(size_t)D_MODEL* KDIM];
__device__ __align__(128) __half g_qkv16[(size_t)M_ROWS * TDQ];
__device__ __align__(128) __half g_at16 [(size_t)M_ROWS * D_MODEL];

// ---------------------------------------------------------------------------
// Helpers
// ---------------------------------------------------------------------------
__device__ __forceinline__ uint32_t smem_u32(const void* p) {
    uint32_t a;
    asm("{ .reg .u64 t; cvta.to.shared.u64 t, %1; cvt.u32.u64 %0, t; }"
        : "=r"(a) : "l"(p));
    return a;
}

#define CP_ASYNC16(saddr, gptr) \
    asm volatile("cp.async.cg.shared.global [%0], [%1], 16;" :: "r"(saddr), "l"(gptr))
#define CP_COMMIT() asm volatile("cp.async.commit_group;" ::: "memory")
#define CP_WAIT0()  asm volatile("cp.async.wait_group 0;" ::: "memory")
#define CP_WAIT1()  asm volatile("cp.async.wait_group 1;" ::: "memory")

__device__ __forceinline__ void ldsm4(uint32_t* r, uint32_t addr) {
    asm volatile("ldmatrix.sync.aligned.m8n8.x4.shared.b16 {%0,%1,%2,%3}, [%4];"
                 : "=r"(r[0]), "=r"(r[1]), "=r"(r[2]), "=r"(r[3]) : "r"(addr));
}
__device__ __forceinline__ void ldsm4t(uint32_t* r, uint32_t addr) {
    asm volatile("ldmatrix.sync.aligned.m8n8.x4.trans.shared.b16 {%0,%1,%2,%3}, [%4];"
                 : "=r"(r[0]), "=r"(r[1]), "=r"(r[2]), "=r"(r[3]) : "r"(addr));
}
__device__ __forceinline__ void mma16816h(float* d, const uint32_t* a,
                                          uint32_t b0, uint32_t b1) {
    asm volatile(
        "mma.sync.aligned.m16n8k16.row.col.f32.f16.f16.f32 "
        "{%0,%1,%2,%3}, {%4,%5,%6,%7}, {%8,%9}, {%0,%1,%2,%3};"
        : "+f"(d[0]), "+f"(d[1]), "+f"(d[2]), "+f"(d[3])
        : "r"(a[0]), "r"(a[1]), "r"(a[2]), "r"(a[3]), "r"(b0), "r"(b1));
}
__device__ __forceinline__ uint32_t pack_h2(float x, float y) {
    __half2 h = __floats2half2_rn(x, y);
    return *(uint32_t*)&h;
}

// ---------------------------------------------------------------------------
// fp32 -> fp16 convert
// ---------------------------------------------------------------------------
__global__ void __launch_bounds__(256)
cvt16(const float4* __restrict__ src, uint2* __restrict__ dst, int n4)
{
    int i = blockIdx.x * blockDim.x + threadIdx.x;
    if (i >= n4) return;
    float4 v = src[i];
    uint2 o;
    o.x = pack_h2(v.x, v.y);
    o.y = pack_h2(v.z, v.w);
    dst[i] = o;
}

// ---------------------------------------------------------------------------
// fp16 HMMA GEMM (NT): C[m,n] = sum_k A[m,k]*B[n,k] + bias[n]
// 128(M) x 256(N) CTA tile, BK=64, 8 warps 2(M)x4(N), 64x64 warp tile.
// 3-stage cp.async pipeline; B fragments double-buffered across ks.
// ---------------------------------------------------------------------------
#define ROWB   144                      // 128B data + 16 pad
#define A_ARR  (128 * ROWB)             // 18432
#define B_ARR  (256 * ROWB)             // 36864
#define STAGE_B (A_ARR + B_ARR)         // 55296
#define GEMM_SMEM (3 * STAGE_B)         // 165888

__global__ void __launch_bounds__(256, 1)
gemm_hmma(const __half* __restrict__ A, const __half* __restrict__ B,
          const float* __restrict__ bias, void* __restrict__ Cv,
          int M, int N, int K, int half_out)
{
    extern __shared__ char sm[];
    const int tid  = threadIdx.x;
    const int wid  = tid >> 5;
    const int lane = tid & 31;
    const int wm   = wid & 1;           // 0..1 (M)
    const int wn   = wid >> 1;          // 0..3 (N)
    const int row0 = blockIdx.y * 128;
    const int col0 = blockIdx.x * 256;

    const uint32_t smb = smem_u32(sm);

    auto ld_chunk = [&](int i, int stage) {
        const int k0 = i * 64;
        uint32_t sb = smb + stage * STAGE_B;
        #pragma unroll
        for (int rep = 0; rep < 4; rep++) {        // A: 128 rows x 8 chunks
            int idx = tid + rep * 256;
            int row = idx >> 3, ch = idx & 7;
            size_t go = (size_t)(row0 + row) * K + k0 + ch * 8;
            CP_ASYNC16(sb + row * ROWB + ch * 16, A + go);
        }
        #pragma unroll
        for (int rep = 0; rep < 8; rep++) {        // B: 256 rows x 8 chunks
            int idx = tid + rep * 256;
            int row = idx >> 3, ch = idx & 7;
            size_t go = (size_t)(col0 + row) * K + k0 + ch * 8;
            CP_ASYNC16(sb + A_ARR + row * ROWB + ch * 16, B + go);
        }
    };

    float acc[4][8][4];
    #pragma unroll
    for (int i = 0; i < 4; i++)
        #pragma unroll
        for (int j = 0; j < 8; j++)
            #pragma unroll
            for (int v = 0; v < 4; v++) acc[i][j][v] = 0.f;

    // x4 lane addressing: row = lane&15, k-half = lane>>4
    const uint32_t aoff = (uint32_t)((wm * 64 + (lane & 15)) * ROWB + (lane >> 4) * 16);
    const uint32_t boff = (uint32_t)((wn * 64 + (lane & 15)) * ROWB + (lane >> 4) * 16);

    const int NC = K / 64;
    ld_chunk(0, 0); CP_COMMIT();
    ld_chunk(1, 1); CP_COMMIT();

    int st = 0;
    for (int i = 0; i < NC; i++) {
        if (i < NC - 1) { CP_WAIT1(); } else { CP_WAIT0(); }
        __syncthreads();
        if (i + 2 < NC) {
            int s2 = st + 2; if (s2 >= 3) s2 -= 3;
            ld_chunk(i + 2, s2);
            CP_COMMIT();
        }

        const uint32_t sA = smb + st * STAGE_B;
        const uint32_t sB = sA + A_ARR;

        // B-fragment double buffer across ks
        uint32_t bb[2][4][4];
        #pragma unroll
        for (int fp = 0; fp < 4; fp++)
            ldsm4(bb[0][fp], sB + boff + fp * 16 * ROWB);

        #pragma unroll
        for (int ks = 0; ks < 4; ks++) {
            const int cur = ks & 1;
            uint32_t ah[4][4];
            #pragma unroll
            for (int fi = 0; fi < 4; fi++)
                ldsm4(ah[fi], sA + aoff + fi * 16 * ROWB + ks * 32);
            if (ks < 3) {
                #pragma unroll
                for (int fp = 0; fp < 4; fp++)
                    ldsm4(bb[cur ^ 1][fp], sB + boff + fp * 16 * ROWB + (ks + 1) * 32);
            }
            #pragma unroll
            for (int fi = 0; fi < 4; fi++)
                #pragma unroll
                for (int fp = 0; fp < 4; fp++) {
                    mma16816h(acc[fi][2 * fp],     ah[fi], bb[cur][fp][0], bb[cur][fp][2]);
                    mma16816h(acc[fi][2 * fp + 1], ah[fi], bb[cur][fp][1], bb[cur][fp][3]);
                }
        }
        if (++st == 3) st = 0;
    }

    if (half_out) {
        __half* C = (__half*)Cv;
        #pragma unroll
        for (int fi = 0; fi < 4; fi++) {
            const int r = row0 + wm * 64 + fi * 16 + (lane >> 2);
            #pragma unroll
            for (int fj = 0; fj < 8; fj++) {
                const int cc = col0 + wn * 64 + fj * 8 + (lane & 3) * 2;
                float2 bbv = *(const float2*)&bias[cc];
                *(uint32_t*)&C[(size_t)r * N + cc] =
                    pack_h2(acc[fi][fj][0] + bbv.x, acc[fi][fj][1] + bbv.y);
                *(uint32_t*)&C[(size_t)(r + 8) * N + cc] =
                    pack_h2(acc[fi][fj][2] + bbv.x, acc[fi][fj][3] + bbv.y);
            }
        }
    } else {
        float* C = (float*)Cv;
        #pragma unroll
        for (int fi = 0; fi < 4; fi++) {
            const int r = row0 + wm * 64 + fi * 16 + (lane >> 2);
            #pragma unroll
            for (int fj = 0; fj < 8; fj++) {
                const int cc = col0 + wn * 64 + fj * 8 + (lane & 3) * 2;
                float2 bbv = *(const float2*)&bias[cc];
                float2 v0 = make_float2(acc[fi][fj][0] + bbv.x, acc[fi][fj][1] + bbv.y);
                float2 v1 = make_float2(acc[fi][fj][2] + bbv.x, acc[fi][fj][3] + bbv.y);
                *(float2*)&C[(size_t)r * N + cc]       = v0;
                *(float2*)&C[(size_t)(r + 8) * N + cc] = v1;
            }
        }
    }
}

// ---------------------------------------------------------------------------
// Flash attention, fp16 HMMA. 128 q rows/CTA, 8 warps x 16 rows, 64-key
// tiles, 3-stage cp.async. Q/K/V all straight from qkv16:
//   K+V are contiguous 256B per row -> single merged cp.async region.
//   V^T fragments via ldmatrix.x4.trans (no transposed copy needed).
// ---------------------------------------------------------------------------
#define QROW     144
#define Q_ARR    (128 * QROW)          // 18432
#define KVROW    272                   // 256B data + 16 pad (68 words: conflict-free)
#define KV_STAGE (64 * KVROW)          // 17408
#define ATTN_SMEM (Q_ARR + 3 * KV_STAGE)   // 70656

__global__ void __launch_bounds__(256, 2)
attn_mma(const __half* __restrict__ qkv, __half* __restrict__ outp)
{
    extern __shared__ char sm[];
    const uint32_t smb = smem_u32(sm);
    const int tid  = threadIdx.x;
    const int wid  = tid >> 5;
    const int lane = tid & 31;
    const int bh = blockIdx.y;
    const int qb = blockIdx.x;
    const int b  = bh >> 4;
    const int h  = bh & 15;

    const __half* Qp  = qkv + ((size_t)(b * S_LEN + qb * 128)) * TDQ + h * 3 * HEAD_D;
    const __half* KVb = qkv + ((size_t)(b * S_LEN)) * TDQ + h * 3 * HEAD_D + HEAD_D;

    auto ld_tile = [&](int kt, int st) {
        const int k0 = kt * 64;
        const uint32_t sb = smb + Q_ARR + st * KV_STAGE;
        #pragma unroll
        for (int rep = 0; rep < 4; rep++) {
            int idx = tid + rep * 256;        // 0..1023
            int row = idx >> 4;               // 0..63
            int ch  = idx & 15;               // 16 x 16B = 256B (K then V)
            CP_ASYNC16(sb + row * KVROW + ch * 16,
                       KVb + (size_t)(k0 + row) * TDQ + ch * 8);
        }
    };

    // group 0: Q + tile 0; group 1: tile 1
    #pragma unroll
    for (int rep = 0; rep < 4; rep++) {
        int idx = tid + rep * 256;
        int row = idx >> 3;
        int ch  = idx & 7;
        CP_ASYNC16(smb + row * QROW + ch * 16, Qp + (size_t)row * TDQ + ch * 8);
    }
    ld_tile(0, 0);
    CP_COMMIT();
    ld_tile(1, 1);
    CP_COMMIT();

    CP_WAIT1();
    __syncthreads();

    // Q fragments; scale by 1/8 (exact power of two)
    const uint32_t qbase = smb + (uint32_t)((wid * 16 + (lane & 15)) * QROW
                                            + (lane >> 4) * 16);
    uint32_t qf[4][4];
    const __half2 sc = __half2half2(__float2half(0.125f));
    #pragma unroll
    for (int kk = 0; kk < 4; kk++) {
        ldsm4(qf[kk], qbase + kk * 32);
        #pragma unroll
        for (int r = 0; r < 4; r++) {
            __half2 hv = *(__half2*)&qf[kk][r];
            hv = __hmul2(hv, sc);
            qf[kk][r] = *(uint32_t*)&hv;
        }
    }

    float o[8][4];
    #pragma unroll
    for (int nf = 0; nf < 8; nf++)
        #pragma unroll
        for (int v = 0; v < 4; v++) o[nf][v] = 0.f;
    float m0 = -1e30f, m1 = -1e30f, l0 = 0.f, l1 = 0.f;

    // K fragments (non-trans): rows = keys
    const uint32_t bo_k = (uint32_t)((lane & 15) * KVROW + (lane >> 4) * 16);
    // V fragments (trans): rows = keys, cols = dims; V data starts at byte 128
    const uint32_t bo_v = (uint32_t)((((lane & 7) | (((lane >> 3) & 1) << 3))) * KVROW
                                     + (lane >> 4) * 16 + 128);
    const int NT = S_LEN / 64;

    int st = 0;
    for (int kt = 0; kt < NT; kt++) {
        if (kt < NT - 1) { CP_WAIT1(); } else { CP_WAIT0(); }
        __syncthreads();
        if (kt + 2 < NT) {
            int s2 = st + 2; if (s2 >= 3) s2 -= 3;
            ld_tile(kt + 2, s2);
            CP_COMMIT();
        }

        const uint32_t base_kv = smb + Q_ARR + st * KV_STAGE;

        float s_[8][4];
        #pragma unroll
        for (int nf = 0; nf < 8; nf++)
            #pragma unroll
            for (int v = 0; v < 4; v++) s_[nf][v] = 0.f;

        // S = Q K^T : K tile rows = keys (n), cols = dims (k)
        #pragma unroll
        for (int np = 0; np < 4; np++) {
            #pragma unroll
            for (int kk = 0; kk < 4; kk++) {
                uint32_t kb[4];
                ldsm4(kb, base_kv + bo_k + np * 16 * KVROW + kk * 32);
                mma16816h(s_[2 * np],     qf[kk], kb[0], kb[2]);
                mma16816h(s_[2 * np + 1], qf[kk], kb[1], kb[3]);
            }
        }

        float tm0 = -1e30f, tm1 = -1e30f;
        #pragma unroll
        for (int nf = 0; nf < 8; nf++) {
            tm0 = fmaxf(tm0, fmaxf(s_[nf][0], s_[nf][1]));
            tm1 = fmaxf(tm1, fmaxf(s_[nf][2], s_[nf][3]));
        }
        tm0 = fmaxf(tm0, __shfl_xor_sync(0xffffffffu, tm0, 1));
        tm0 = fmaxf(tm0, __shfl_xor_sync(0xffffffffu, tm0, 2));
        tm1 = fmaxf(tm1, __shfl_xor_sync(0xffffffffu, tm1, 1));
        tm1 = fmaxf(tm1, __shfl_xor_sync(0xffffffffu, tm1, 2));

        const float mn0 = fmaxf(m0, tm0);
        const float mn1 = fmaxf(m1, tm1);
        const float a0 = __expf(m0 - mn0);
        const float a1 = __expf(m1 - mn1);
        m0 = mn0; m1 = mn1;

        float sum0 = 0.f, sum1 = 0.f;
        #pragma unroll
        for (int nf = 0; nf < 8; nf++) {
            s_[nf][0] = __expf(s_[nf][0] - m0);
            s_[nf][1] = __expf(s_[nf][1] - m0);
            s_[nf][2] = __expf(s_[nf][2] - m1);
            s_[nf][3] = __expf(s_[nf][3] - m1);
            sum0 += s_[nf][0] + s_[nf][1];
            sum1 += s_[nf][2] + s_[nf][3];
        }
        sum0 += __shfl_xor_sync(0xffffffffu, sum0, 1);
        sum0 += __shfl_xor_sync(0xffffffffu, sum0, 2);
        sum1 += __shfl_xor_sync(0xffffffffu, sum1, 1);
        sum1 += __shfl_xor_sync(0xffffffffu, sum1, 2);
        l0 = l0 * a0 + sum0;
        l1 = l1 * a1 + sum1;

        #pragma unroll
        for (int nf = 0; nf < 8; nf++) {
            o[nf][0] *= a0; o[nf][1] *= a0;
            o[nf][2] *= a1; o[nf][3] *= a1;
        }

        uint32_t pa[4][4];
        #pragma unroll
        for (int kk = 0; kk < 4; kk++) {
            const int n0 = 2 * kk, n1 = 2 * kk + 1;
            pa[kk][0] = pack_h2(s_[n0][0], s_[n0][1]);
            pa[kk][1] = pack_h2(s_[n0][2], s_[n0][3]);
            pa[kk][2] = pack_h2(s_[n1][0], s_[n1][1]);
            pa[kk][3] = pack_h2(s_[n1][2], s_[n1][3]);
        }

        // O += P V : V^T fragments via ldsm4.trans on [key][dim] tile.
        // dd = 16-dim block, kk = 16-key block.
        #pragma unroll
        for (int dd = 0; dd < 4; dd++) {
            #pragma unroll
            for (int kk = 0; kk < 4; kk++) {
                uint32_t vb[4];
                ldsm4t(vb, base_kv + bo_v + kk * 16 * KVROW + dd * 32);
                mma16816h(o[2 * dd],     pa[kk], vb[0], vb[1]);
                mma16816h(o[2 * dd + 1], pa[kk], vb[2], vb[3]);
            }
        }

        if (++st == 3) st = 0;
    }

    const float inv0 = 1.f / l0;
    const float inv1 = 1.f / l1;
    const int r0 = qb * 128 + wid * 16 + (lane >> 2);
    const size_t tok0 = (size_t)(b * S_LEN + r0) * D_MODEL;
    const size_t tok1 = (size_t)(b * S_LEN + r0 + 8) * D_MODEL;
    #pragma unroll
    for (int nf = 0; nf < 8; nf++) {
        const int col = h * HEAD_D + nf * 8 + (lane & 3) * 2;
        *(uint32_t*)(outp + tok0 + col) = pack_h2(o[nf][0] * inv0, o[nf][1] * inv0);
        *(uint32_t*)(outp + tok1 + col) = pack_h2(o[nf][2] * inv1, o[nf][3] * inv1);
    }
}

// ---------------------------------------------------------------------------
extern "C" void kernel_launch(void* const* d_in, const int* in_sizes, int n_in,
                              void* d_out, int out_size)
{
    const float* x     = (const float*)d_in[0];
    const float* w_qkv = (const float*)d_in[1];
    const float* b_qkv = (const float*)d_in[2];
    const float* w_o   = (const float*)d_in[3];
    const float* b_o   = (const float*)d_in[4];
    float* out = (float*)d_out;

    __half *x16, *wq16, *wo16, *qkv16, *at16;
    cudaGetSymbolAddress((void**)&x16,   g_x16);
    cudaGetSymbolAddress((void**)&wq16,  g_wq16);
    cudaGetSymbolAddress((void**)&wo16,  g_wo16);
    cudaGetSymbolAddress((void**)&qkv16, g_qkv16);
    cudaGetSymbolAddress((void**)&at16,  g_at16);

    cudaFuncSetAttribute(gemm_hmma, cudaFuncAttributeMaxDynamicSharedMemorySize, GEMM_SMEM);
    cudaFuncSetAttribute(attn_mma,  cudaFuncAttributeMaxDynamicSharedMemorySize, ATTN_SMEM);

    // fp32 -> fp16 converts
    {
        int n4 = M_ROWS * KDIM / 4;
        cvt16<<<(n4 + 255) / 256, 256>>>((const float4*)x, (uint2*)x16, n4);
    }
    {
        int n4 = TDQ * KDIM / 4;
        cvt16<<<(n4 + 255) / 256, 256>>>((const float4*)w_qkv, (uint2*)wq16, n4);
    }
    {
        int n4 = D_MODEL * KDIM / 4;
        cvt16<<<(n4 + 255) / 256, 256>>>((const float4*)w_o, (uint2*)wo16, n4);
    }

    // 1) QKV projection -> fp16
    {
        dim3 grid(TDQ / 256, M_ROWS / 128);
        gemm_hmma<<<grid, 256, GEMM_SMEM>>>(x16, wq16, b_qkv, qkv16,
                                            M_ROWS, TDQ, KDIM, 1);
    }
    // 2) tensor-core flash attention -> fp16 [token][1024]
    {
        dim3 grid(S_LEN / 128, BH);
        attn_mma<<<grid, 256, ATTN_SMEM>>>(qkv16, at16);
    }
    // 3) output projection -> fp32
    {
        dim3 grid(D_MODEL / 256, M_ROWS / 128);
        gemm_hmma<<<grid, 256, GEMM_SMEM>>>(at16, wo16, b_o, out,
                                            M_ROWS, D_MODEL, KDIM, 0);
    }
}